// round 15
// baseline (speedup 1.0000x reference)
#include <cuda_runtime.h>
#include <cuda_fp16.h>
#include <math.h>
#include <float.h>
#include <stdint.h>

#define BATCH 8192
#define DIM   128
#define NCLS  1000
#define LDH 136                       /* padded halves per row (272B) */
#define TILEH (128 * LDH)             /* halves per tile (34816 B)    */
#define SMEM_BYTES (3 * TILEH * 2)
#define NCTA 296
#define MAXFLAG 64

// ---- device scratch ----
__device__ __half   g_embh[BATCH * DIM];
__device__ float    g_sq[BATCH];
__device__ uint32_t g_packed[BATCH];   // (dot+2 bits & ~0x1FFF) | (8191-idx)
__device__ uint32_t g_patch[BATCH];    // (d2 bits & ~0x1FFF) | idx  (min)
__device__ int      g_pi[BATCH];
__device__ int      g_ni[BATCH];
__device__ int      g_ccount[NCLS];
__device__ int      g_coff[NCLS];
__device__ int      g_crows[BATCH];
__device__ int      g_flagrows[MAXFLAG];
__device__ int      g_nflag;
__device__ int      g_done;
__device__ int      g_mine_done;
__device__ float    g_ce_part[BATCH / 8];
__device__ float    g_tri_part[BATCH / 8];
__device__ int      g_cnt_part[BATCH / 8];

// ================= helpers =================
__device__ __forceinline__ uint32_t smem_u32(const void* p) {
    uint32_t a;
    asm("{ .reg .u64 t; cvta.to.shared.u64 t, %1; cvt.u32.u64 %0, t; }" : "=r"(a) : "l"(p));
    return a;
}
__device__ __forceinline__ void cp16(void* s, const void* g) {
    uint32_t sa = smem_u32(s);
    asm volatile("cp.async.cg.shared.global [%0], [%1], 16;" :: "r"(sa), "l"(g));
}
__device__ __forceinline__ void cpcommit() { asm volatile("cp.async.commit_group;"); }
template<int N> __device__ __forceinline__ void cpwait() {
    asm volatile("cp.async.wait_group %0;" :: "n"(N));
}
__device__ __forceinline__ void mma16(float* c, const uint32_t* a, const uint32_t* b) {
    asm volatile(
        "mma.sync.aligned.m16n8k16.row.col.f32.f16.f16.f32 "
        "{%0,%1,%2,%3}, {%4,%5,%6,%7}, {%8,%9}, {%0,%1,%2,%3};"
        : "+f"(c[0]), "+f"(c[1]), "+f"(c[2]), "+f"(c[3])
        : "r"(a[0]), "r"(a[1]), "r"(a[2]), "r"(a[3]), "r"(b[0]), "r"(b[1]));
}
__device__ __forceinline__ void ldsm4(uint32_t* r, uint32_t addr) {
    asm volatile("ldmatrix.sync.aligned.m8n8.x4.shared.b16 {%0,%1,%2,%3}, [%4];"
        : "=r"(r[0]), "=r"(r[1]), "=r"(r[2]), "=r"(r[3]) : "r"(addr));
}
__device__ __forceinline__ void dec_tile(int L, int& it, int& jt) {
    int c = 0, r = 0;
#pragma unroll 1
    while (c + (64 - r) <= L) { c += 64 - r; r++; }
    it = r; jt = r + (L - c);
}

// ---------------------------------------------------------------------------
// prep: sq norms + f32->f16 conversion + zero scratch (warp per row)
// ---------------------------------------------------------------------------
__global__ void prep_kernel(const float* __restrict__ emb) {
    int wid = threadIdx.x >> 5, lane = threadIdx.x & 31;
    int row = blockIdx.x * 8 + wid;
    int gt = blockIdx.x * 256 + threadIdx.x;
    if (gt < BATCH) g_packed[gt] = 0u;
    if (gt == 0) { g_nflag = 0; g_done = 0; g_mine_done = 0; }
    float4 v = *reinterpret_cast<const float4*>(emb + (size_t)row * DIM + lane * 4);
    __half2 h01 = __floats2half2_rn(v.x, v.y);
    __half2 h23 = __floats2half2_rn(v.z, v.w);
    uint2 hw = make_uint2(*(uint32_t*)&h01, *(uint32_t*)&h23);
    *reinterpret_cast<uint2*>(&g_embh[(size_t)row * DIM + lane * 4]) = hw;
    float s = v.x * v.x + v.y * v.y + v.z * v.z + v.w * v.w;
#pragma unroll
    for (int off = 16; off; off >>= 1) s += __shfl_xor_sync(0xffffffffu, s, off);
    if (lane == 0) g_sq[row] = s;
}

// ---------------------------------------------------------------------------
// cross entropy, float4 loads, per-block partial (no atomics)
// ---------------------------------------------------------------------------
__global__ void ce_kernel(const float* __restrict__ logits, const int* __restrict__ labels) {
    __shared__ float warp_loss[8];
    int wid = threadIdx.x >> 5, lane = threadIdx.x & 31;
    int row = blockIdx.x * 8 + wid;
    const float* x = logits + (size_t)row * NCLS;
    float m = -FLT_MAX, s = 0.f, sx = 0.f;
#pragma unroll
    for (int i = 0; i < 8; i++) {
        int c4 = lane + 32 * i;
        if (c4 < 250) {
            float4 v = __ldg(reinterpret_cast<const float4*>(x) + c4);
            sx += v.x + v.y + v.z + v.w;
            float ml = fmaxf(fmaxf(v.x, v.y), fmaxf(v.z, v.w));
            float sl = __expf(v.x - ml) + __expf(v.y - ml) +
                       __expf(v.z - ml) + __expf(v.w - ml);
            float nm = fmaxf(m, ml);
            s = s * __expf(m - nm) + sl * __expf(ml - nm);
            m = nm;
        }
    }
#pragma unroll
    for (int off = 16; off; off >>= 1) {
        float om = __shfl_xor_sync(0xffffffffu, m, off);
        float os = __shfl_xor_sync(0xffffffffu, s, off);
        float nm = fmaxf(m, om);
        s = s * __expf(m - nm) + os * __expf(om - nm);
        m = nm;
        sx += __shfl_xor_sync(0xffffffffu, sx, off);
    }
    if (lane == 0) {
        float lse = m + logf(s);
        float xl  = __ldg(x + labels[row]);
        warp_loss[wid] = 0.9f * (lse - xl) + 0.1f * (lse - sx * (1.0f / (float)NCLS));
    }
    __syncthreads();
    if (threadIdx.x == 0) {
        float b = 0.f;
#pragma unroll
        for (int w = 0; w < 8; w++) b += warp_loss[w];
        g_ce_part[blockIdx.x] = b;
    }
}

// ---------------------------------------------------------------------------
// fused smem histogram + shuffle scan + smem-counter scatter (single block)
// ---------------------------------------------------------------------------
__global__ void class_kernel(const int* __restrict__ labels) {
    __shared__ int hist[NCLS];
    __shared__ int fill[NCLS];
    __shared__ int wsum[32];
    int t = threadIdx.x, lane = t & 31, w = t >> 5;
    if (t < NCLS) { hist[t] = 0; fill[t] = 0; }
    __syncthreads();
#pragma unroll
    for (int i = 0; i < 8; i++) atomicAdd(&hist[labels[t + 1024 * i]], 1);
    __syncthreads();
    int v = (t < NCLS) ? hist[t] : 0;
    int x = v;
#pragma unroll
    for (int o = 1; o < 32; o <<= 1) {
        int y = __shfl_up_sync(0xffffffffu, x, o);
        if (lane >= o) x += y;
    }
    if (lane == 31) wsum[w] = x;
    __syncthreads();
    if (w == 0) {
        int sv = wsum[lane];
#pragma unroll
        for (int o = 1; o < 32; o <<= 1) {
            int y = __shfl_up_sync(0xffffffffu, sv, o);
            if (lane >= o) sv += y;
        }
        wsum[lane] = sv;
    }
    __syncthreads();
    int offset = (w > 0) ? wsum[w - 1] : 0;
    int myoff = x + offset - v;
    if (t < NCLS) { g_coff[t] = myoff; g_ccount[t] = v; hist[t] = myoff; }
    __syncthreads();
#pragma unroll
    for (int i = 0; i < 8; i++) {
        int idx = t + 1024 * i;
        int lab = labels[idx];
        int pos = hist[lab] + atomicAdd(&fill[lab], 1);
        g_crows[pos] = idx;
    }
}

// ---------------------------------------------------------------------------
// exact hardest positive: warp per ANCHOR
// ---------------------------------------------------------------------------
__global__ void pos_kernel(const float* __restrict__ emb, const int* __restrict__ labels) {
    int wid = threadIdx.x >> 5, lane = threadIdx.x & 31;
    int row = blockIdx.x * 8 + wid;
    int lab = labels[row];
    int off = g_coff[lab], cnt = g_ccount[lab];
    float4 av = *reinterpret_cast<const float4*>(emb + (size_t)row * DIM + lane * 4);
    float sqa = g_sq[row];
    float best = -FLT_MAX; int besti = -1;
    for (int bi = 0; bi < cnt; bi++) {
        int b = g_crows[off + bi];
        if (b == row) continue;
        float4 bv = *reinterpret_cast<const float4*>(emb + (size_t)b * DIM + lane * 4);
        float d = av.x * bv.x + av.y * bv.y + av.z * bv.z + av.w * bv.w;
#pragma unroll
        for (int o = 16; o; o >>= 1) d += __shfl_xor_sync(0xffffffffu, d, o);
        float d2 = sqa + g_sq[b] - 2.f * d;
        if (d2 > best || (d2 == best && b < besti)) { best = d2; besti = b; }
    }
    if (lane == 0) g_pi[row] = besti;
}

// ---------------------------------------------------------------------------
// symmetric fp16 tensor-core Gram + bidirectional packed max-dot mining
// 256 threads/CTA, 64x32 warp tiles, ldmatrix fragments, bias in accumulator.
// Epilogue runs BEFORE the post-MMA barrier; flag scan fused as last-CTA tail.
// ---------------------------------------------------------------------------
template<bool DIAG>
__device__ __forceinline__ void mine_rows(
    const float acc[4][4][4], const uint32_t jc[8], uint32_t run[8],
    int wi, int wj, int lane)
{
#pragma unroll
    for (int mf = 0; mf < 4; mf++) {
#pragma unroll
        for (int nf = 0; nf < 4; nf++) {
#pragma unroll
            for (int e = 0; e < 4; e++) {
                int h = e >> 1, eb = e & 1;
                uint32_t bits = __float_as_uint(acc[mf][nf][e]);   // bias pre-added in acc
                uint32_t pk = (bits & 0xFFFFE000u) | jc[nf * 2 + eb];
                if (DIAG) {
                    int cl = wj * 32 + nf * 8 + 2 * (lane & 3) + eb;
                    int rl = wi * 64 + mf * 16 + (lane >> 2) + 8 * h;
                    if (cl == rl) pk = 0u;
                }
                int q = mf * 2 + h;
                run[q] = run[q] > pk ? run[q] : pk;
            }
        }
    }
}

__device__ __forceinline__ void mine_cols(
    const float acc[4][4][4], int it, int jt, int wi, int wj, int lane)
{
    uint32_t colrun[8];
#pragma unroll
    for (int q = 0; q < 8; q++) colrun[q] = 0u;
    uint32_t ic[8];
#pragma unroll
    for (int mf = 0; mf < 4; mf++)
#pragma unroll
        for (int h = 0; h < 2; h++)
            ic[mf * 2 + h] =
                (uint32_t)(8191 - (it * 128 + wi * 64 + mf * 16 + (lane >> 2) + 8 * h));
#pragma unroll
    for (int mf = 0; mf < 4; mf++)
#pragma unroll
        for (int nf = 0; nf < 4; nf++)
#pragma unroll
            for (int e = 0; e < 4; e++) {
                int h = e >> 1, eb = e & 1;
                uint32_t bits = __float_as_uint(acc[mf][nf][e]);   // bias pre-added in acc
                uint32_t pk = (bits & 0xFFFFE000u) | ic[mf * 2 + h];
                int q = nf * 2 + eb;
                colrun[q] = colrun[q] > pk ? colrun[q] : pk;
            }
#pragma unroll
    for (int q = 0; q < 8; q++) {
        uint32_t v = colrun[q];
        v = max(v, __shfl_xor_sync(0xffffffffu, v, 4));
        v = max(v, __shfl_xor_sync(0xffffffffu, v, 8));
        v = max(v, __shfl_xor_sync(0xffffffffu, v, 16));
        colrun[q] = v;
    }
    if ((lane >> 2) == 0) {
#pragma unroll
        for (int nf = 0; nf < 4; nf++)
#pragma unroll
            for (int eb = 0; eb < 2; eb++) {
                int col = jt * 128 + wj * 32 + nf * 8 + 2 * lane + eb;
                atomicMax(&g_packed[col], colrun[nf * 2 + eb]);
            }
    }
}

__device__ __forceinline__ void flush_rows(uint32_t run[8], int it, int wi, int lane) {
#pragma unroll
    for (int q = 0; q < 8; q++) {
        uint32_t v = run[q];
        v = max(v, __shfl_xor_sync(0xffffffffu, v, 1));
        v = max(v, __shfl_xor_sync(0xffffffffu, v, 2));
        run[q] = v;
    }
    if ((lane & 3) == 0) {
#pragma unroll
        for (int mf = 0; mf < 4; mf++)
#pragma unroll
            for (int h = 0; h < 2; h++) {
                int row = it * 128 + wi * 64 + mf * 16 + (lane >> 2) + 8 * h;
                atomicMax(&g_packed[row], run[mf * 2 + h]);
            }
    }
}

__global__ __launch_bounds__(256, 2)
void mine_kernel(const int* __restrict__ labels) {
    extern __shared__ __half smh[];
    __half* sA = smh;
    __half* sB[2] = { smh + TILEH, smh + 2 * TILEH };
    __shared__ int s_last;

    const int tid = threadIdx.x, lane = tid & 31, wid = tid >> 5;
    const int wi = wid & 1, wj = wid >> 1;
    const int k = blockIdx.x;
    const int start = 7 * k + (k < 8 ? k : 8);
    const int cnt = 7 + (k < 8 ? 1 : 0);

    // ldmatrix per-lane address offsets (bytes), row-major tiles, stride LDH
    const int g8 = lane >> 3, l7 = lane & 7;
    const uint32_t sA_u = smem_u32(sA);
    const uint32_t sB_u[2] = { smem_u32(sB[0]), smem_u32(sB[1]) };
    uint32_t aOff[4], bOff[2];
#pragma unroll
    for (int mf = 0; mf < 4; mf++)
        aOff[mf] = (uint32_t)(((wi * 64 + mf * 16 + (g8 & 1) * 8 + l7) * LDH
                               + (g8 >> 1) * 8) * 2);
#pragma unroll
    for (int p = 0; p < 2; p++)
        bOff[p] = (uint32_t)(((wj * 32 + p * 16 + (g8 >> 1) * 8 + l7) * LDH
                               + (g8 & 1) * 8) * 2);

    auto loadA = [&](int it) {
#pragma unroll
        for (int i = 0; i < 8; i++) {
            int idx = tid + i * 256, r = idx >> 4, c = idx & 15;
            cp16(&sA[r * LDH + c * 8], g_embh + (size_t)(it * 128 + r) * DIM + c * 8);
        }
    };
    auto loadB = [&](__half* dst, int jt) {
#pragma unroll
        for (int i = 0; i < 8; i++) {
            int idx = tid + i * 256, r = idx >> 4, c = idx & 15;
            cp16(&dst[r * LDH + c * 8], g_embh + (size_t)(jt * 128 + r) * DIM + c * 8);
        }
    };

    int it0, jt0;
    dec_tile(start, it0, jt0);
    loadA(it0); loadB(sB[0], jt0);
    cpcommit();
    if (cnt > 1) { int i1, j1; dec_tile(start + 1, i1, j1); loadB(sB[1], j1); }
    cpcommit();

    int cur_it = it0;
    uint32_t run[8];
#pragma unroll
    for (int q = 0; q < 8; q++) run[q] = 0u;

    for (int s = 0; s < cnt; s++) {
        int it, jt;
        dec_tile(start + s, it, jt);
        if (it != cur_it) {
            flush_rows(run, cur_it, wi, lane);
#pragma unroll
            for (int q = 0; q < 8; q++) run[q] = 0u;
            cpwait<0>(); __syncthreads();
            loadA(it); cpcommit();
            cpwait<0>(); __syncthreads();
            cur_it = it;
        } else {
            cpwait<1>(); __syncthreads();
        }
        const uint32_t bBu = sB_u[s & 1];

        float acc[4][4][4];
#pragma unroll
        for (int mf = 0; mf < 4; mf++)
#pragma unroll
            for (int nf = 0; nf < 4; nf++)
#pragma unroll
                for (int e = 0; e < 4; e++) acc[mf][nf][e] = 2.0f;  // bias folded in

#pragma unroll
        for (int ks = 0; ks < 8; ks++) {
            const uint32_t koff = (uint32_t)(ks * 16 * 2);
            uint32_t a[4][4], b[4][2];
#pragma unroll
            for (int mf = 0; mf < 4; mf++)
                ldsm4(a[mf], sA_u + aOff[mf] + koff);
#pragma unroll
            for (int p = 0; p < 2; p++) {
                uint32_t t4[4];
                ldsm4(t4, bBu + bOff[p] + koff);
                b[p * 2][0] = t4[0]; b[p * 2][1] = t4[1];
                b[p * 2 + 1][0] = t4[2]; b[p * 2 + 1][1] = t4[3];
            }
#pragma unroll
            for (int mf = 0; mf < 4; mf++)
#pragma unroll
                for (int nf = 0; nf < 4; nf++)
                    mma16(acc[mf][nf], a[mf], b[nf]);
        }

        // epilogue BEFORE the barrier: per-warp independent work evens out
        // barrier arrival; no smem touched here.
        uint32_t jc[8];
#pragma unroll
        for (int nf = 0; nf < 4; nf++)
#pragma unroll
            for (int eb = 0; eb < 2; eb++)
                jc[nf * 2 + eb] =
                    (uint32_t)(8191 - (jt * 128 + wj * 32 + nf * 8 + 2 * (lane & 3) + eb));

        if (it == jt) {
            mine_rows<true>(acc, jc, run, wi, wj, lane);
        } else {
            mine_rows<false>(acc, jc, run, wi, wj, lane);
            mine_cols(acc, it, jt, wi, wj, lane);
        }

        __syncthreads();   // all warps done reading B stage (s&1)

        if (s + 2 < cnt) {
            int i2, j2;
            dec_tile(start + s + 2, i2, j2);
            loadB(sB[s & 1], j2);
            cpcommit();
        }
    }
    flush_rows(run, cur_it, wi, lane);

    // ---- fused flag scan: last CTA classifies all rows ----
    __threadfence();
    __syncthreads();
    if (tid == 0) s_last = (atomicAdd(&g_mine_done, 1) == NCTA - 1) ? 1 : 0;
    __syncthreads();
    if (s_last) {
        __threadfence();
        for (int row = tid; row < BATCH; row += 256) {
            uint32_t pk = g_packed[row];
            int ni = 8191 - (int)(pk & 0x1FFFu);
            if (labels[ni] == labels[row]) {
                int sidx = atomicAdd(&g_nflag, 1);
                if (sidx < MAXFLAG) {
                    g_flagrows[sidx] = row;
                    g_ni[row] = -1;
                    g_patch[row] = 0xFFFFFFFFu;
                } else {
                    g_ni[row] = ni;   // overflow fallback (never expected)
                }
            } else {
                g_ni[row] = ni;
            }
        }
    }
}

// ---------------------------------------------------------------------------
// parallel exact rescan, coalesced: grid (MAXFLAG, 32); warp handles one j at
// a time with all 32 lanes loading that row (512B coalesced) + shfl reduce.
// ---------------------------------------------------------------------------
__global__ void patch_kernel(const float* __restrict__ emb, const int* __restrict__ labels) {
    int f = blockIdx.x;
    if (f >= g_nflag) return;
    int row = g_flagrows[f];
    int li = labels[row];
    int tid = threadIdx.x, lane = tid & 31, w = tid >> 5;
    float4 av = *reinterpret_cast<const float4*>(emb + (size_t)row * DIM + lane * 4);
    float sqr = g_sq[row];
    uint32_t best = 0xFFFFFFFFu;
    int jbase = blockIdx.y * 256 + w * 32;
#pragma unroll 4
    for (int kk = 0; kk < 32; kk++) {
        int j = jbase + kk;
        float4 bv = *reinterpret_cast<const float4*>(emb + (size_t)j * DIM + lane * 4);
        float d = av.x * bv.x + av.y * bv.y + av.z * bv.z + av.w * bv.w;
#pragma unroll
        for (int o = 16; o; o >>= 1) d += __shfl_xor_sync(0xffffffffu, d, o);
        if (labels[j] != li) {
            float d2 = fmaxf(sqr + g_sq[j] - 2.f * d, 0.f);
            uint32_t pk = (__float_as_uint(d2) & 0xFFFFE000u) | (uint32_t)j;
            best = min(best, pk);
        }
    }
    if (lane == 0) atomicMin(&g_patch[row], best);
}

// ---------------------------------------------------------------------------
// finalize + fused final reduction (last block reduces all partials)
// ---------------------------------------------------------------------------
__global__ void finalize_kernel(const float* __restrict__ emb, float* __restrict__ out) {
    __shared__ float s_tri[8];
    __shared__ int   s_cnt[8];
    __shared__ int   s_last;
    int wid = threadIdx.x >> 5, lane = threadIdx.x & 31;
    int row = blockIdx.x * 8 + wid;
    int pi = g_pi[row];
    int ni = g_ni[row];
    if (ni < 0) ni = (int)(g_patch[row] & 0x1FFFu);
    bool valid = (pi >= 0);
    float per = 0.f;
    if (valid) {
        const float eps = 1e-6f;
        float4 a = *reinterpret_cast<const float4*>(emb + (size_t)row * DIM + lane * 4);
        float4 p = *reinterpret_cast<const float4*>(emb + (size_t)pi * DIM + lane * 4);
        float4 n = *reinterpret_cast<const float4*>(emb + (size_t)ni * DIM + lane * 4);
        float dx = a.x - p.x + eps, dy = a.y - p.y + eps, dz = a.z - p.z + eps, dw = a.w - p.w + eps;
        float sp = dx * dx + dy * dy + dz * dz + dw * dw;
        dx = a.x - n.x + eps; dy = a.y - n.y + eps; dz = a.z - n.z + eps; dw = a.w - n.w + eps;
        float sn = dx * dx + dy * dy + dz * dz + dw * dw;
#pragma unroll
        for (int off = 16; off; off >>= 1) {
            sp += __shfl_xor_sync(0xffffffffu, sp, off);
            sn += __shfl_xor_sync(0xffffffffu, sn, off);
        }
        per = fmaxf(sqrtf(sp) - sqrtf(sn) + 0.5f, 0.f);
    }
    if (lane == 0) { s_tri[wid] = valid ? per : 0.f; s_cnt[wid] = valid ? 1 : 0; }
    __syncthreads();
    if (threadIdx.x == 0) {
        float b = 0.f; int c = 0;
#pragma unroll
        for (int w = 0; w < 8; w++) { b += s_tri[w]; c += s_cnt[w]; }
        g_tri_part[blockIdx.x] = b;
        g_cnt_part[blockIdx.x] = c;
        __threadfence();
        s_last = (atomicAdd(&g_done, 1) == (int)gridDim.x - 1);
    }
    __syncthreads();
    if (s_last) {
        __shared__ float sce[8], str[8]; __shared__ int scn[8];
        int t = threadIdx.x;
        float ce = 0.f, tri = 0.f; int c = 0;
#pragma unroll
        for (int i = 0; i < 4; i++) {
            int idx = t + i * 256;
            ce  += g_ce_part[idx];
            tri += g_tri_part[idx];
            c   += g_cnt_part[idx];
        }
#pragma unroll
        for (int o = 16; o; o >>= 1) {
            ce  += __shfl_xor_sync(0xffffffffu, ce, o);
            tri += __shfl_xor_sync(0xffffffffu, tri, o);
            c   += __shfl_xor_sync(0xffffffffu, c, o);
        }
        if (lane == 0) { sce[wid] = ce; str[wid] = tri; scn[wid] = c; }
        __syncthreads();
        if (t == 0) {
            float tc = 0.f, tt = 0.f; int tn = 0;
#pragma unroll
            for (int i = 0; i < 8; i++) { tc += sce[i]; tt += str[i]; tn += scn[i]; }
            out[0] = tc * (1.0f / (float)BATCH) + (tn > 0 ? tt / (float)tn : 0.f);
        }
    }
}

// ---------------------------------------------------------------------------
extern "C" void kernel_launch(void* const* d_in, const int* in_sizes, int n_in,
                              void* d_out, int out_size) {
    const float* logits = (const float*)d_in[0];
    const float* emb    = (const float*)d_in[1];
    const int*   labels = (const int*)d_in[2];
    float* out = (float*)d_out;

    // Handles created exactly ONCE (first/correctness call), reused on the
    // capture call so no resources are created after the pre-capture baseline.
    static cudaStream_t s1 = nullptr, s2 = nullptr;
    static cudaEvent_t e0 = nullptr, e_prep = nullptr, e_pos = nullptr, e_ce = nullptr;
    if (s1 == nullptr) {
        cudaStreamCreateWithFlags(&s1, cudaStreamNonBlocking);
        cudaStreamCreateWithFlags(&s2, cudaStreamNonBlocking);
        cudaEventCreateWithFlags(&e0,     cudaEventDisableTiming);
        cudaEventCreateWithFlags(&e_prep, cudaEventDisableTiming);
        cudaEventCreateWithFlags(&e_pos,  cudaEventDisableTiming);
        cudaEventCreateWithFlags(&e_ce,   cudaEventDisableTiming);
        cudaFuncSetAttribute(mine_kernel, cudaFuncAttributeMaxDynamicSharedMemorySize, SMEM_BYTES);
    }

    cudaEventRecord(e0, 0);
    cudaStreamWaitEvent(s1, e0, 0);
    cudaStreamWaitEvent(s2, e0, 0);

    // main chain (flag fused into mine's last CTA)
    prep_kernel<<<BATCH / 8, 256>>>(emb);
    cudaEventRecord(e_prep, 0);
    mine_kernel<<<NCTA, 256, SMEM_BYTES>>>(labels);
    {
        dim3 pg(MAXFLAG, 32);
        patch_kernel<<<pg, 256>>>(emb, labels);
    }

    // side chain 1: cross entropy
    ce_kernel<<<BATCH / 8, 256, 0, s1>>>(logits, labels);
    cudaEventRecord(e_ce, s1);

    // side chain 2: class grouping + hardest positive
    class_kernel<<<1, 1024, 0, s2>>>(labels);
    cudaStreamWaitEvent(s2, e_prep, 0);
    pos_kernel<<<BATCH / 8, 256, 0, s2>>>(emb, labels);
    cudaEventRecord(e_pos, s2);

    // join (finalize's last block also does the final reduction incl. ce)
    cudaStreamWaitEvent(0, e_pos, 0);
    cudaStreamWaitEvent(0, e_ce, 0);
    finalize_kernel<<<BATCH / 8, 256>>>(emb, out);
}

// round 16
// speedup vs baseline: 1.1892x; 1.1892x over previous
#include <cuda_runtime.h>
#include <cuda_fp16.h>
#include <math.h>
#include <float.h>
#include <stdint.h>

#define BATCH 8192
#define DIM   128
#define NCLS  1000
#define LDH 136                       /* padded halves per row (272B) */
#define TILEH (128 * LDH)             /* halves per tile (34816 B)    */
#define SMEM_BYTES (3 * TILEH * 2)
#define NCTA 296
#define MAXFLAG 64

// ---- device scratch ----
__device__ __half   g_embh[BATCH * DIM];
__device__ float    g_sq[BATCH];
__device__ uint32_t g_packed[BATCH];   // (dot+2 bits & ~0x1FFF) | (8191-idx)
__device__ uint32_t g_patch[BATCH];    // (d2 bits & ~0x1FFF) | idx  (min)
__device__ int      g_pi[BATCH];
__device__ int      g_ni[BATCH];
__device__ int      g_ccount[NCLS];
__device__ int      g_coff[NCLS];
__device__ int      g_crows[BATCH];
__device__ int      g_flagrows[MAXFLAG];
__device__ int      g_nflag;
__device__ float    g_ce_part[BATCH / 8];
__device__ float    g_tri_part[BATCH / 8];
__device__ int      g_cnt_part[BATCH / 8];

// ================= helpers =================
__device__ __forceinline__ uint32_t smem_u32(const void* p) {
    uint32_t a;
    asm("{ .reg .u64 t; cvta.to.shared.u64 t, %1; cvt.u32.u64 %0, t; }" : "=r"(a) : "l"(p));
    return a;
}
__device__ __forceinline__ void cp16(void* s, const void* g) {
    uint32_t sa = smem_u32(s);
    asm volatile("cp.async.cg.shared.global [%0], [%1], 16;" :: "r"(sa), "l"(g));
}
__device__ __forceinline__ void cpcommit() { asm volatile("cp.async.commit_group;"); }
template<int N> __device__ __forceinline__ void cpwait() {
    asm volatile("cp.async.wait_group %0;" :: "n"(N));
}
__device__ __forceinline__ void mma16(float* c, const uint32_t* a, const uint32_t* b) {
    asm volatile(
        "mma.sync.aligned.m16n8k16.row.col.f32.f16.f16.f32 "
        "{%0,%1,%2,%3}, {%4,%5,%6,%7}, {%8,%9}, {%0,%1,%2,%3};"
        : "+f"(c[0]), "+f"(c[1]), "+f"(c[2]), "+f"(c[3])
        : "r"(a[0]), "r"(a[1]), "r"(a[2]), "r"(a[3]), "r"(b[0]), "r"(b[1]));
}
__device__ __forceinline__ void ldsm4(uint32_t* r, uint32_t addr) {
    asm volatile("ldmatrix.sync.aligned.m8n8.x4.shared.b16 {%0,%1,%2,%3}, [%4];"
        : "=r"(r[0]), "=r"(r[1]), "=r"(r[2]), "=r"(r[3]) : "r"(addr));
}
__device__ __forceinline__ void dec_tile(int L, int& it, int& jt) {
    int c = 0, r = 0;
#pragma unroll 1
    while (c + (64 - r) <= L) { c += 64 - r; r++; }
    it = r; jt = r + (L - c);
}

// ---------------------------------------------------------------------------
// prep: sq norms + f32->f16 conversion + zero scratch (warp per row)
// ---------------------------------------------------------------------------
__global__ void prep_kernel(const float* __restrict__ emb) {
    int wid = threadIdx.x >> 5, lane = threadIdx.x & 31;
    int row = blockIdx.x * 8 + wid;
    int gt = blockIdx.x * 256 + threadIdx.x;
    if (gt < BATCH) g_packed[gt] = 0u;
    if (gt == 0) g_nflag = 0;
    float4 v = *reinterpret_cast<const float4*>(emb + (size_t)row * DIM + lane * 4);
    __half2 h01 = __floats2half2_rn(v.x, v.y);
    __half2 h23 = __floats2half2_rn(v.z, v.w);
    uint2 hw = make_uint2(*(uint32_t*)&h01, *(uint32_t*)&h23);
    *reinterpret_cast<uint2*>(&g_embh[(size_t)row * DIM + lane * 4]) = hw;
    float s = v.x * v.x + v.y * v.y + v.z * v.z + v.w * v.w;
#pragma unroll
    for (int off = 16; off; off >>= 1) s += __shfl_xor_sync(0xffffffffu, s, off);
    if (lane == 0) g_sq[row] = s;
}

// ---------------------------------------------------------------------------
// cross entropy, float4 loads, per-block partial (no atomics)
// ---------------------------------------------------------------------------
__global__ void ce_kernel(const float* __restrict__ logits, const int* __restrict__ labels) {
    __shared__ float warp_loss[8];
    int wid = threadIdx.x >> 5, lane = threadIdx.x & 31;
    int row = blockIdx.x * 8 + wid;
    const float* x = logits + (size_t)row * NCLS;
    float m = -FLT_MAX, s = 0.f, sx = 0.f;
#pragma unroll
    for (int i = 0; i < 8; i++) {
        int c4 = lane + 32 * i;
        if (c4 < 250) {
            float4 v = __ldg(reinterpret_cast<const float4*>(x) + c4);
            sx += v.x + v.y + v.z + v.w;
            float ml = fmaxf(fmaxf(v.x, v.y), fmaxf(v.z, v.w));
            float sl = __expf(v.x - ml) + __expf(v.y - ml) +
                       __expf(v.z - ml) + __expf(v.w - ml);
            float nm = fmaxf(m, ml);
            s = s * __expf(m - nm) + sl * __expf(ml - nm);
            m = nm;
        }
    }
#pragma unroll
    for (int off = 16; off; off >>= 1) {
        float om = __shfl_xor_sync(0xffffffffu, m, off);
        float os = __shfl_xor_sync(0xffffffffu, s, off);
        float nm = fmaxf(m, om);
        s = s * __expf(m - nm) + os * __expf(om - nm);
        m = nm;
        sx += __shfl_xor_sync(0xffffffffu, sx, off);
    }
    if (lane == 0) {
        float lse = m + logf(s);
        float xl  = __ldg(x + labels[row]);
        warp_loss[wid] = 0.9f * (lse - xl) + 0.1f * (lse - sx * (1.0f / (float)NCLS));
    }
    __syncthreads();
    if (threadIdx.x == 0) {
        float b = 0.f;
#pragma unroll
        for (int w = 0; w < 8; w++) b += warp_loss[w];
        g_ce_part[blockIdx.x] = b;
    }
}

// ---------------------------------------------------------------------------
// fused smem histogram + shuffle scan + smem-counter scatter (single block)
// ---------------------------------------------------------------------------
__global__ void class_kernel(const int* __restrict__ labels) {
    __shared__ int hist[NCLS];
    __shared__ int fill[NCLS];
    __shared__ int wsum[32];
    int t = threadIdx.x, lane = t & 31, w = t >> 5;
    if (t < NCLS) { hist[t] = 0; fill[t] = 0; }
    __syncthreads();
#pragma unroll
    for (int i = 0; i < 8; i++) atomicAdd(&hist[labels[t + 1024 * i]], 1);
    __syncthreads();
    int v = (t < NCLS) ? hist[t] : 0;
    int x = v;
#pragma unroll
    for (int o = 1; o < 32; o <<= 1) {
        int y = __shfl_up_sync(0xffffffffu, x, o);
        if (lane >= o) x += y;
    }
    if (lane == 31) wsum[w] = x;
    __syncthreads();
    if (w == 0) {
        int sv = wsum[lane];
#pragma unroll
        for (int o = 1; o < 32; o <<= 1) {
            int y = __shfl_up_sync(0xffffffffu, sv, o);
            if (lane >= o) sv += y;
        }
        wsum[lane] = sv;
    }
    __syncthreads();
    int offset = (w > 0) ? wsum[w - 1] : 0;
    int myoff = x + offset - v;
    if (t < NCLS) { g_coff[t] = myoff; g_ccount[t] = v; hist[t] = myoff; }
    __syncthreads();
#pragma unroll
    for (int i = 0; i < 8; i++) {
        int idx = t + 1024 * i;
        int lab = labels[idx];
        int pos = hist[lab] + atomicAdd(&fill[lab], 1);
        g_crows[pos] = idx;
    }
}

// ---------------------------------------------------------------------------
// exact hardest positive: warp per ANCHOR
// ---------------------------------------------------------------------------
__global__ void pos_kernel(const float* __restrict__ emb, const int* __restrict__ labels) {
    int wid = threadIdx.x >> 5, lane = threadIdx.x & 31;
    int row = blockIdx.x * 8 + wid;
    int lab = labels[row];
    int off = g_coff[lab], cnt = g_ccount[lab];
    float4 av = *reinterpret_cast<const float4*>(emb + (size_t)row * DIM + lane * 4);
    float sqa = g_sq[row];
    float best = -FLT_MAX; int besti = -1;
    for (int bi = 0; bi < cnt; bi++) {
        int b = g_crows[off + bi];
        if (b == row) continue;
        float4 bv = *reinterpret_cast<const float4*>(emb + (size_t)b * DIM + lane * 4);
        float d = av.x * bv.x + av.y * bv.y + av.z * bv.z + av.w * bv.w;
#pragma unroll
        for (int o = 16; o; o >>= 1) d += __shfl_xor_sync(0xffffffffu, d, o);
        float d2 = sqa + g_sq[b] - 2.f * d;
        if (d2 > best || (d2 == best && b < besti)) { best = d2; besti = b; }
    }
    if (lane == 0) g_pi[row] = besti;
}

// ---------------------------------------------------------------------------
// symmetric fp16 tensor-core Gram + bidirectional packed max-dot mining
// 256 threads/CTA, 64x32 warp tiles, ldmatrix fragments, bias in accumulator
// (R14 winning configuration: MMA -> sync -> prefetch -> epilogue)
// ---------------------------------------------------------------------------
template<bool DIAG>
__device__ __forceinline__ void mine_rows(
    const float acc[4][4][4], const uint32_t jc[8], uint32_t run[8],
    int wi, int wj, int lane)
{
#pragma unroll
    for (int mf = 0; mf < 4; mf++) {
#pragma unroll
        for (int nf = 0; nf < 4; nf++) {
#pragma unroll
            for (int e = 0; e < 4; e++) {
                int h = e >> 1, eb = e & 1;
                uint32_t bits = __float_as_uint(acc[mf][nf][e]);   // bias pre-added in acc
                uint32_t pk = (bits & 0xFFFFE000u) | jc[nf * 2 + eb];
                if (DIAG) {
                    int cl = wj * 32 + nf * 8 + 2 * (lane & 3) + eb;
                    int rl = wi * 64 + mf * 16 + (lane >> 2) + 8 * h;
                    if (cl == rl) pk = 0u;
                }
                int q = mf * 2 + h;
                run[q] = run[q] > pk ? run[q] : pk;
            }
        }
    }
}

__device__ __forceinline__ void mine_cols(
    const float acc[4][4][4], int it, int jt, int wi, int wj, int lane)
{
    uint32_t colrun[8];
#pragma unroll
    for (int q = 0; q < 8; q++) colrun[q] = 0u;
    uint32_t ic[8];
#pragma unroll
    for (int mf = 0; mf < 4; mf++)
#pragma unroll
        for (int h = 0; h < 2; h++)
            ic[mf * 2 + h] =
                (uint32_t)(8191 - (it * 128 + wi * 64 + mf * 16 + (lane >> 2) + 8 * h));
#pragma unroll
    for (int mf = 0; mf < 4; mf++)
#pragma unroll
        for (int nf = 0; nf < 4; nf++)
#pragma unroll
            for (int e = 0; e < 4; e++) {
                int h = e >> 1, eb = e & 1;
                uint32_t bits = __float_as_uint(acc[mf][nf][e]);   // bias pre-added in acc
                uint32_t pk = (bits & 0xFFFFE000u) | ic[mf * 2 + h];
                int q = nf * 2 + eb;
                colrun[q] = colrun[q] > pk ? colrun[q] : pk;
            }
#pragma unroll
    for (int q = 0; q < 8; q++) {
        uint32_t v = colrun[q];
        v = max(v, __shfl_xor_sync(0xffffffffu, v, 4));
        v = max(v, __shfl_xor_sync(0xffffffffu, v, 8));
        v = max(v, __shfl_xor_sync(0xffffffffu, v, 16));
        colrun[q] = v;
    }
    if ((lane >> 2) == 0) {
#pragma unroll
        for (int nf = 0; nf < 4; nf++)
#pragma unroll
            for (int eb = 0; eb < 2; eb++) {
                int col = jt * 128 + wj * 32 + nf * 8 + 2 * lane + eb;
                atomicMax(&g_packed[col], colrun[nf * 2 + eb]);
            }
    }
}

__device__ __forceinline__ void flush_rows(uint32_t run[8], int it, int wi, int lane) {
#pragma unroll
    for (int q = 0; q < 8; q++) {
        uint32_t v = run[q];
        v = max(v, __shfl_xor_sync(0xffffffffu, v, 1));
        v = max(v, __shfl_xor_sync(0xffffffffu, v, 2));
        run[q] = v;
    }
    if ((lane & 3) == 0) {
#pragma unroll
        for (int mf = 0; mf < 4; mf++)
#pragma unroll
            for (int h = 0; h < 2; h++) {
                int row = it * 128 + wi * 64 + mf * 16 + (lane >> 2) + 8 * h;
                atomicMax(&g_packed[row], run[mf * 2 + h]);
            }
    }
}

__global__ __launch_bounds__(256, 2)
void mine_kernel() {
    extern __shared__ __half smh[];
    __half* sA = smh;
    __half* sB[2] = { smh + TILEH, smh + 2 * TILEH };

    const int tid = threadIdx.x, lane = tid & 31, wid = tid >> 5;
    const int wi = wid & 1, wj = wid >> 1;
    const int k = blockIdx.x;
    const int start = 7 * k + (k < 8 ? k : 8);
    const int cnt = 7 + (k < 8 ? 1 : 0);

    const int g8 = lane >> 3, l7 = lane & 7;
    const uint32_t sA_u = smem_u32(sA);
    const uint32_t sB_u[2] = { smem_u32(sB[0]), smem_u32(sB[1]) };
    uint32_t aOff[4], bOff[2];
#pragma unroll
    for (int mf = 0; mf < 4; mf++)
        aOff[mf] = (uint32_t)(((wi * 64 + mf * 16 + (g8 & 1) * 8 + l7) * LDH
                               + (g8 >> 1) * 8) * 2);
#pragma unroll
    for (int p = 0; p < 2; p++)
        bOff[p] = (uint32_t)(((wj * 32 + p * 16 + (g8 >> 1) * 8 + l7) * LDH
                               + (g8 & 1) * 8) * 2);

    auto loadA = [&](int it) {
#pragma unroll
        for (int i = 0; i < 8; i++) {
            int idx = tid + i * 256, r = idx >> 4, c = idx & 15;
            cp16(&sA[r * LDH + c * 8], g_embh + (size_t)(it * 128 + r) * DIM + c * 8);
        }
    };
    auto loadB = [&](__half* dst, int jt) {
#pragma unroll
        for (int i = 0; i < 8; i++) {
            int idx = tid + i * 256, r = idx >> 4, c = idx & 15;
            cp16(&dst[r * LDH + c * 8], g_embh + (size_t)(jt * 128 + r) * DIM + c * 8);
        }
    };

    int it0, jt0;
    dec_tile(start, it0, jt0);
    loadA(it0); loadB(sB[0], jt0);
    cpcommit();
    if (cnt > 1) { int i1, j1; dec_tile(start + 1, i1, j1); loadB(sB[1], j1); }
    cpcommit();

    int cur_it = it0;
    uint32_t run[8];
#pragma unroll
    for (int q = 0; q < 8; q++) run[q] = 0u;

    for (int s = 0; s < cnt; s++) {
        int it, jt;
        dec_tile(start + s, it, jt);
        if (it != cur_it) {
            flush_rows(run, cur_it, wi, lane);
#pragma unroll
            for (int q = 0; q < 8; q++) run[q] = 0u;
            cpwait<0>(); __syncthreads();
            loadA(it); cpcommit();
            cpwait<0>(); __syncthreads();
            cur_it = it;
        } else {
            cpwait<1>(); __syncthreads();
        }
        const uint32_t bBu = sB_u[s & 1];

        float acc[4][4][4];
#pragma unroll
        for (int mf = 0; mf < 4; mf++)
#pragma unroll
            for (int nf = 0; nf < 4; nf++)
#pragma unroll
                for (int e = 0; e < 4; e++) acc[mf][nf][e] = 2.0f;  // bias folded in

#pragma unroll
        for (int ks = 0; ks < 8; ks++) {
            const uint32_t koff = (uint32_t)(ks * 16 * 2);
            uint32_t a[4][4], b[4][2];
#pragma unroll
            for (int mf = 0; mf < 4; mf++)
                ldsm4(a[mf], sA_u + aOff[mf] + koff);
#pragma unroll
            for (int p = 0; p < 2; p++) {
                uint32_t t4[4];
                ldsm4(t4, bBu + bOff[p] + koff);
                b[p * 2][0] = t4[0]; b[p * 2][1] = t4[1];
                b[p * 2 + 1][0] = t4[2]; b[p * 2 + 1][1] = t4[3];
            }
#pragma unroll
            for (int mf = 0; mf < 4; mf++)
#pragma unroll
                for (int nf = 0; nf < 4; nf++)
                    mma16(acc[mf][nf], a[mf], b[nf]);
        }
        __syncthreads();

        if (s + 2 < cnt) {
            int i2, j2;
            dec_tile(start + s + 2, i2, j2);
            loadB(sB[s & 1], j2);
            cpcommit();
        }

        uint32_t jc[8];
#pragma unroll
        for (int nf = 0; nf < 4; nf++)
#pragma unroll
            for (int eb = 0; eb < 2; eb++)
                jc[nf * 2 + eb] =
                    (uint32_t)(8191 - (jt * 128 + wj * 32 + nf * 8 + 2 * (lane & 3) + eb));

        if (it == jt) {
            mine_rows<true>(acc, jc, run, wi, wj, lane);
        } else {
            mine_rows<false>(acc, jc, run, wi, wj, lane);
            mine_cols(acc, it, jt, wi, wj, lane);
        }
    }
    flush_rows(run, cur_it, wi, lane);
}

// ---------------------------------------------------------------------------
__global__ void flag_kernel(const int* __restrict__ labels) {
    int row = blockIdx.x * 256 + threadIdx.x;
    uint32_t pk = g_packed[row];
    int ni = 8191 - (int)(pk & 0x1FFFu);
    if (labels[ni] == labels[row]) {
        int s = atomicAdd(&g_nflag, 1);
        if (s < MAXFLAG) {
            g_flagrows[s] = row;
            g_ni[row] = -1;
            g_patch[row] = 0xFFFFFFFFu;
        } else {
            g_ni[row] = ni;   // overflow fallback (never expected)
        }
    } else {
        g_ni[row] = ni;
    }
}

// ---------------------------------------------------------------------------
// parallel exact rescan, coalesced: grid (MAXFLAG, 32)
// ---------------------------------------------------------------------------
__global__ void patch_kernel(const float* __restrict__ emb, const int* __restrict__ labels) {
    int f = blockIdx.x;
    if (f >= g_nflag) return;
    int row = g_flagrows[f];
    int li = labels[row];
    int tid = threadIdx.x, lane = tid & 31, w = tid >> 5;
    float4 av = *reinterpret_cast<const float4*>(emb + (size_t)row * DIM + lane * 4);
    float sqr = g_sq[row];
    uint32_t best = 0xFFFFFFFFu;
    int jbase = blockIdx.y * 256 + w * 32;
#pragma unroll 4
    for (int kk = 0; kk < 32; kk++) {
        int j = jbase + kk;
        float4 bv = *reinterpret_cast<const float4*>(emb + (size_t)j * DIM + lane * 4);
        float d = av.x * bv.x + av.y * bv.y + av.z * bv.z + av.w * bv.w;
#pragma unroll
        for (int o = 16; o; o >>= 1) d += __shfl_xor_sync(0xffffffffu, d, o);
        if (labels[j] != li) {
            float d2 = fmaxf(sqr + g_sq[j] - 2.f * d, 0.f);
            uint32_t pk = (__float_as_uint(d2) & 0xFFFFE000u) | (uint32_t)j;
            best = min(best, pk);
        }
    }
    if (lane == 0) atomicMin(&g_patch[row], best);
}

// ---------------------------------------------------------------------------
// finalize_part: triplet contributions for NON-flagged rows (runs || patch)
// ---------------------------------------------------------------------------
__global__ void finalize_part_kernel(const float* __restrict__ emb) {
    __shared__ float s_tri[8];
    __shared__ int   s_cnt[8];
    int wid = threadIdx.x >> 5, lane = threadIdx.x & 31;
    int row = blockIdx.x * 8 + wid;
    int pi = g_pi[row];
    int ni = g_ni[row];
    bool valid = (pi >= 0) && (ni >= 0);   // flagged rows (ni<0) handled in combine
    float per = 0.f;
    if (valid) {
        const float eps = 1e-6f;
        float4 a = *reinterpret_cast<const float4*>(emb + (size_t)row * DIM + lane * 4);
        float4 p = *reinterpret_cast<const float4*>(emb + (size_t)pi * DIM + lane * 4);
        float4 n = *reinterpret_cast<const float4*>(emb + (size_t)ni * DIM + lane * 4);
        float dx = a.x - p.x + eps, dy = a.y - p.y + eps, dz = a.z - p.z + eps, dw = a.w - p.w + eps;
        float sp = dx * dx + dy * dy + dz * dz + dw * dw;
        dx = a.x - n.x + eps; dy = a.y - n.y + eps; dz = a.z - n.z + eps; dw = a.w - n.w + eps;
        float sn = dx * dx + dy * dy + dz * dz + dw * dw;
#pragma unroll
        for (int off = 16; off; off >>= 1) {
            sp += __shfl_xor_sync(0xffffffffu, sp, off);
            sn += __shfl_xor_sync(0xffffffffu, sn, off);
        }
        per = fmaxf(sqrtf(sp) - sqrtf(sn) + 0.5f, 0.f);
    }
    if (lane == 0) { s_tri[wid] = valid ? per : 0.f; s_cnt[wid] = valid ? 1 : 0; }
    __syncthreads();
    if (threadIdx.x == 0) {
        float b = 0.f; int c = 0;
#pragma unroll
        for (int w = 0; w < 8; w++) { b += s_tri[w]; c += s_cnt[w]; }
        g_tri_part[blockIdx.x] = b;
        g_cnt_part[blockIdx.x] = c;
    }
}

// ---------------------------------------------------------------------------
// combine: flagged-row triplets (warp per row, from g_patch) + full reduction
// ---------------------------------------------------------------------------
__global__ void combine_kernel(const float* __restrict__ emb, float* __restrict__ out) {
    __shared__ float s_extra[32];
    __shared__ int   s_ecnt[32];
    __shared__ float sce[32], str[32]; __shared__ int scn[32];
    int t = threadIdx.x, lane = t & 31, w = t >> 5;
    int nf = g_nflag; if (nf > MAXFLAG) nf = MAXFLAG;

    float extra = 0.f; int ecnt = 0;
    for (int f = w; f < nf; f += 32) {
        int row = g_flagrows[f];
        int pi = g_pi[row];
        if (pi >= 0) {
            int ni = (int)(g_patch[row] & 0x1FFFu);
            const float eps = 1e-6f;
            float4 a = *reinterpret_cast<const float4*>(emb + (size_t)row * DIM + lane * 4);
            float4 p = *reinterpret_cast<const float4*>(emb + (size_t)pi * DIM + lane * 4);
            float4 n = *reinterpret_cast<const float4*>(emb + (size_t)ni * DIM + lane * 4);
            float dx = a.x - p.x + eps, dy = a.y - p.y + eps, dz = a.z - p.z + eps, dw = a.w - p.w + eps;
            float sp = dx * dx + dy * dy + dz * dz + dw * dw;
            dx = a.x - n.x + eps; dy = a.y - n.y + eps; dz = a.z - n.z + eps; dw = a.w - n.w + eps;
            float sn = dx * dx + dy * dy + dz * dz + dw * dw;
#pragma unroll
            for (int off = 16; off; off >>= 1) {
                sp += __shfl_xor_sync(0xffffffffu, sp, off);
                sn += __shfl_xor_sync(0xffffffffu, sn, off);
            }
            if (lane == 0) {
                extra += fmaxf(sqrtf(sp) - sqrtf(sn) + 0.5f, 0.f);
                ecnt++;
            }
        }
    }
    if (lane == 0) { s_extra[w] = extra; s_ecnt[w] = ecnt; }

    float ce = g_ce_part[t], tri = g_tri_part[t];
    int c = g_cnt_part[t];
#pragma unroll
    for (int o = 16; o; o >>= 1) {
        ce  += __shfl_xor_sync(0xffffffffu, ce, o);
        tri += __shfl_xor_sync(0xffffffffu, tri, o);
        c   += __shfl_xor_sync(0xffffffffu, c, o);
    }
    if (lane == 0) { sce[w] = ce; str[w] = tri; scn[w] = c; }
    __syncthreads();
    if (t == 0) {
        float tc = 0.f, tt = 0.f; int tn = 0;
#pragma unroll
        for (int i = 0; i < 32; i++) {
            tc += sce[i]; tt += str[i] + s_extra[i]; tn += scn[i] + s_ecnt[i];
        }
        out[0] = tc * (1.0f / (float)BATCH) + (tn > 0 ? tt / (float)tn : 0.f);
    }
}

// ---------------------------------------------------------------------------
extern "C" void kernel_launch(void* const* d_in, const int* in_sizes, int n_in,
                              void* d_out, int out_size) {
    const float* logits = (const float*)d_in[0];
    const float* emb    = (const float*)d_in[1];
    const int*   labels = (const int*)d_in[2];
    float* out = (float*)d_out;

    // Handles created exactly ONCE (first/correctness call), reused on the
    // capture call so no resources are created after the pre-capture baseline.
    static cudaStream_t s1 = nullptr, s2 = nullptr, s3 = nullptr;
    static cudaEvent_t e0 = nullptr, e_prep = nullptr, e_pos = nullptr,
                       e_ce = nullptr, e_flag = nullptr, e_fin = nullptr;
    if (s1 == nullptr) {
        cudaStreamCreateWithFlags(&s1, cudaStreamNonBlocking);
        cudaStreamCreateWithFlags(&s2, cudaStreamNonBlocking);
        cudaStreamCreateWithFlags(&s3, cudaStreamNonBlocking);
        cudaEventCreateWithFlags(&e0,     cudaEventDisableTiming);
        cudaEventCreateWithFlags(&e_prep, cudaEventDisableTiming);
        cudaEventCreateWithFlags(&e_pos,  cudaEventDisableTiming);
        cudaEventCreateWithFlags(&e_ce,   cudaEventDisableTiming);
        cudaEventCreateWithFlags(&e_flag, cudaEventDisableTiming);
        cudaEventCreateWithFlags(&e_fin,  cudaEventDisableTiming);
        cudaFuncSetAttribute(mine_kernel, cudaFuncAttributeMaxDynamicSharedMemorySize, SMEM_BYTES);
    }

    cudaEventRecord(e0, 0);
    cudaStreamWaitEvent(s1, e0, 0);
    cudaStreamWaitEvent(s2, e0, 0);

    // main chain
    prep_kernel<<<BATCH / 8, 256>>>(emb);
    cudaEventRecord(e_prep, 0);
    mine_kernel<<<NCTA, 256, SMEM_BYTES>>>();
    flag_kernel<<<32, 256>>>(labels);
    cudaEventRecord(e_flag, 0);
    {
        dim3 pg(MAXFLAG, 32);
        patch_kernel<<<pg, 256>>>(emb, labels);
    }

    // side chain 1: cross entropy
    ce_kernel<<<BATCH / 8, 256, 0, s1>>>(logits, labels);
    cudaEventRecord(e_ce, s1);

    // side chain 2: class grouping + hardest positive
    class_kernel<<<1, 1024, 0, s2>>>(labels);
    cudaStreamWaitEvent(s2, e_prep, 0);
    pos_kernel<<<BATCH / 8, 256, 0, s2>>>(emb, labels);
    cudaEventRecord(e_pos, s2);

    // side chain 3: finalize for non-flagged rows, overlapped with patch
    cudaStreamWaitEvent(s3, e_flag, 0);
    cudaStreamWaitEvent(s3, e_pos, 0);
    finalize_part_kernel<<<BATCH / 8, 256, 0, s3>>>(emb);
    cudaEventRecord(e_fin, s3);

    // join: combine needs patch (main), finalize_part, ce
    cudaStreamWaitEvent(0, e_fin, 0);
    cudaStreamWaitEvent(0, e_ce, 0);
    combine_kernel<<<1, 1024>>>(emb, out);
}

// round 17
// speedup vs baseline: 1.2552x; 1.0554x over previous
#include <cuda_runtime.h>
#include <cuda_fp16.h>
#include <math.h>
#include <float.h>
#include <stdint.h>

#define BATCH 8192
#define DIM   128
#define NCLS  1000
#define LDH 136                       /* padded halves per row (272B) */
#define TILEH (128 * LDH)             /* halves per tile (34816 B)    */
#define SMEM_BYTES (3 * TILEH * 2)
#define NCTA 296
#define MAXFLAG 64

// ---- device scratch ----
__device__ __half   g_embh[BATCH * DIM];
__device__ float    g_sq[BATCH];
__device__ uint32_t g_packed[BATCH];   // (dot+2 bits & ~0x1FFF) | (8191-idx)
__device__ uint32_t g_patch[BATCH];    // (d2 bits & ~0x1FFF) | idx  (min)
__device__ int      g_pi[BATCH];
__device__ int      g_ni[BATCH];
__device__ int      g_ccount[NCLS];
__device__ int      g_coff[NCLS];
__device__ int      g_crows[BATCH];
__device__ int      g_flagrows[MAXFLAG];
__device__ int      g_nflag;
__device__ int      g_done;
__device__ float    g_ce_part[BATCH / 8];
__device__ float    g_tri_part[BATCH / 8];
__device__ int      g_cnt_part[BATCH / 8];

// ================= helpers =================
__device__ __forceinline__ uint32_t smem_u32(const void* p) {
    uint32_t a;
    asm("{ .reg .u64 t; cvta.to.shared.u64 t, %1; cvt.u32.u64 %0, t; }" : "=r"(a) : "l"(p));
    return a;
}
__device__ __forceinline__ void cp16(void* s, const void* g) {
    uint32_t sa = smem_u32(s);
    asm volatile("cp.async.cg.shared.global [%0], [%1], 16;" :: "r"(sa), "l"(g));
}
__device__ __forceinline__ void cpcommit() { asm volatile("cp.async.commit_group;"); }
template<int N> __device__ __forceinline__ void cpwait() {
    asm volatile("cp.async.wait_group %0;" :: "n"(N));
}
__device__ __forceinline__ void mma16(float* c, const uint32_t* a, const uint32_t* b) {
    asm volatile(
        "mma.sync.aligned.m16n8k16.row.col.f32.f16.f16.f32 "
        "{%0,%1,%2,%3}, {%4,%5,%6,%7}, {%8,%9}, {%0,%1,%2,%3};"
        : "+f"(c[0]), "+f"(c[1]), "+f"(c[2]), "+f"(c[3])
        : "r"(a[0]), "r"(a[1]), "r"(a[2]), "r"(a[3]), "r"(b[0]), "r"(b[1]));
}
__device__ __forceinline__ void ldsm4(uint32_t* r, uint32_t addr) {
    asm volatile("ldmatrix.sync.aligned.m8n8.x4.shared.b16 {%0,%1,%2,%3}, [%4];"
        : "=r"(r[0]), "=r"(r[1]), "=r"(r[2]), "=r"(r[3]) : "r"(addr));
}
__device__ __forceinline__ void dec_tile(int L, int& it, int& jt) {
    int c = 0, r = 0;
#pragma unroll 1
    while (c + (64 - r) <= L) { c += 64 - r; r++; }
    it = r; jt = r + (L - c);
}

// ---------------------------------------------------------------------------
// prep: sq norms + f32->f16 conversion + zero scratch (warp per row)
// ---------------------------------------------------------------------------
__global__ void prep_kernel(const float* __restrict__ emb) {
    int wid = threadIdx.x >> 5, lane = threadIdx.x & 31;
    int row = blockIdx.x * 8 + wid;
    int gt = blockIdx.x * 256 + threadIdx.x;
    if (gt < BATCH) g_packed[gt] = 0u;
    if (gt == 0) { g_nflag = 0; g_done = 0; }
    float4 v = *reinterpret_cast<const float4*>(emb + (size_t)row * DIM + lane * 4);
    __half2 h01 = __floats2half2_rn(v.x, v.y);
    __half2 h23 = __floats2half2_rn(v.z, v.w);
    uint2 hw = make_uint2(*(uint32_t*)&h01, *(uint32_t*)&h23);
    *reinterpret_cast<uint2*>(&g_embh[(size_t)row * DIM + lane * 4]) = hw;
    float s = v.x * v.x + v.y * v.y + v.z * v.z + v.w * v.w;
#pragma unroll
    for (int off = 16; off; off >>= 1) s += __shfl_xor_sync(0xffffffffu, s, off);
    if (lane == 0) g_sq[row] = s;
}

// ---------------------------------------------------------------------------
// cross entropy, float4 loads, per-block partial (no atomics)
// ---------------------------------------------------------------------------
__global__ void ce_kernel(const float* __restrict__ logits, const int* __restrict__ labels) {
    __shared__ float warp_loss[8];
    int wid = threadIdx.x >> 5, lane = threadIdx.x & 31;
    int row = blockIdx.x * 8 + wid;
    const float* x = logits + (size_t)row * NCLS;
    float m = -FLT_MAX, s = 0.f, sx = 0.f;
#pragma unroll
    for (int i = 0; i < 8; i++) {
        int c4 = lane + 32 * i;
        if (c4 < 250) {
            float4 v = __ldg(reinterpret_cast<const float4*>(x) + c4);
            sx += v.x + v.y + v.z + v.w;
            float ml = fmaxf(fmaxf(v.x, v.y), fmaxf(v.z, v.w));
            float sl = __expf(v.x - ml) + __expf(v.y - ml) +
                       __expf(v.z - ml) + __expf(v.w - ml);
            float nm = fmaxf(m, ml);
            s = s * __expf(m - nm) + sl * __expf(ml - nm);
            m = nm;
        }
    }
#pragma unroll
    for (int off = 16; off; off >>= 1) {
        float om = __shfl_xor_sync(0xffffffffu, m, off);
        float os = __shfl_xor_sync(0xffffffffu, s, off);
        float nm = fmaxf(m, om);
        s = s * __expf(m - nm) + os * __expf(om - nm);
        m = nm;
        sx += __shfl_xor_sync(0xffffffffu, sx, off);
    }
    if (lane == 0) {
        float lse = m + logf(s);
        float xl  = __ldg(x + labels[row]);
        warp_loss[wid] = 0.9f * (lse - xl) + 0.1f * (lse - sx * (1.0f / (float)NCLS));
    }
    __syncthreads();
    if (threadIdx.x == 0) {
        float b = 0.f;
#pragma unroll
        for (int w = 0; w < 8; w++) b += warp_loss[w];
        g_ce_part[blockIdx.x] = b;
    }
}

// ---------------------------------------------------------------------------
// fused smem histogram + shuffle scan + smem-counter scatter (single block)
// ---------------------------------------------------------------------------
__global__ void class_kernel(const int* __restrict__ labels) {
    __shared__ int hist[NCLS];
    __shared__ int fill[NCLS];
    __shared__ int wsum[32];
    int t = threadIdx.x, lane = t & 31, w = t >> 5;
    if (t < NCLS) { hist[t] = 0; fill[t] = 0; }
    __syncthreads();
#pragma unroll
    for (int i = 0; i < 8; i++) atomicAdd(&hist[labels[t + 1024 * i]], 1);
    __syncthreads();
    int v = (t < NCLS) ? hist[t] : 0;
    int x = v;
#pragma unroll
    for (int o = 1; o < 32; o <<= 1) {
        int y = __shfl_up_sync(0xffffffffu, x, o);
        if (lane >= o) x += y;
    }
    if (lane == 31) wsum[w] = x;
    __syncthreads();
    if (w == 0) {
        int sv = wsum[lane];
#pragma unroll
        for (int o = 1; o < 32; o <<= 1) {
            int y = __shfl_up_sync(0xffffffffu, sv, o);
            if (lane >= o) sv += y;
        }
        wsum[lane] = sv;
    }
    __syncthreads();
    int offset = (w > 0) ? wsum[w - 1] : 0;
    int myoff = x + offset - v;
    if (t < NCLS) { g_coff[t] = myoff; g_ccount[t] = v; hist[t] = myoff; }
    __syncthreads();
#pragma unroll
    for (int i = 0; i < 8; i++) {
        int idx = t + 1024 * i;
        int lab = labels[idx];
        int pos = hist[lab] + atomicAdd(&fill[lab], 1);
        g_crows[pos] = idx;
    }
}

// ---------------------------------------------------------------------------
// exact hardest positive: warp per ANCHOR
// ---------------------------------------------------------------------------
__global__ void pos_kernel(const float* __restrict__ emb, const int* __restrict__ labels) {
    int wid = threadIdx.x >> 5, lane = threadIdx.x & 31;
    int row = blockIdx.x * 8 + wid;
    int lab = labels[row];
    int off = g_coff[lab], cnt = g_ccount[lab];
    float4 av = *reinterpret_cast<const float4*>(emb + (size_t)row * DIM + lane * 4);
    float sqa = g_sq[row];
    float best = -FLT_MAX; int besti = -1;
    for (int bi = 0; bi < cnt; bi++) {
        int b = g_crows[off + bi];
        if (b == row) continue;
        float4 bv = *reinterpret_cast<const float4*>(emb + (size_t)b * DIM + lane * 4);
        float d = av.x * bv.x + av.y * bv.y + av.z * bv.z + av.w * bv.w;
#pragma unroll
        for (int o = 16; o; o >>= 1) d += __shfl_xor_sync(0xffffffffu, d, o);
        float d2 = sqa + g_sq[b] - 2.f * d;
        if (d2 > best || (d2 == best && b < besti)) { best = d2; besti = b; }
    }
    if (lane == 0) g_pi[row] = besti;
}

// ---------------------------------------------------------------------------
// symmetric fp16 tensor-core Gram + bidirectional packed max-dot mining
// 256 threads/CTA, 64x32 warp tiles, ldmatrix fragments, bias in accumulator.
// Heavy CTAs (8 tiles) spread via k%37==0 so they land on distinct SMs.
// ---------------------------------------------------------------------------
template<bool DIAG>
__device__ __forceinline__ void mine_rows(
    const float acc[4][4][4], const uint32_t jc[8], uint32_t run[8],
    int wi, int wj, int lane)
{
#pragma unroll
    for (int mf = 0; mf < 4; mf++) {
#pragma unroll
        for (int nf = 0; nf < 4; nf++) {
#pragma unroll
            for (int e = 0; e < 4; e++) {
                int h = e >> 1, eb = e & 1;
                uint32_t bits = __float_as_uint(acc[mf][nf][e]);   // bias pre-added in acc
                uint32_t pk = (bits & 0xFFFFE000u) | jc[nf * 2 + eb];
                if (DIAG) {
                    int cl = wj * 32 + nf * 8 + 2 * (lane & 3) + eb;
                    int rl = wi * 64 + mf * 16 + (lane >> 2) + 8 * h;
                    if (cl == rl) pk = 0u;
                }
                int q = mf * 2 + h;
                run[q] = run[q] > pk ? run[q] : pk;
            }
        }
    }
}

__device__ __forceinline__ void mine_cols(
    const float acc[4][4][4], int it, int jt, int wi, int wj, int lane)
{
    uint32_t colrun[8];
#pragma unroll
    for (int q = 0; q < 8; q++) colrun[q] = 0u;
    uint32_t ic[8];
#pragma unroll
    for (int mf = 0; mf < 4; mf++)
#pragma unroll
        for (int h = 0; h < 2; h++)
            ic[mf * 2 + h] =
                (uint32_t)(8191 - (it * 128 + wi * 64 + mf * 16 + (lane >> 2) + 8 * h));
#pragma unroll
    for (int mf = 0; mf < 4; mf++)
#pragma unroll
        for (int nf = 0; nf < 4; nf++)
#pragma unroll
            for (int e = 0; e < 4; e++) {
                int h = e >> 1, eb = e & 1;
                uint32_t bits = __float_as_uint(acc[mf][nf][e]);   // bias pre-added in acc
                uint32_t pk = (bits & 0xFFFFE000u) | ic[mf * 2 + h];
                int q = nf * 2 + eb;
                colrun[q] = colrun[q] > pk ? colrun[q] : pk;
            }
#pragma unroll
    for (int q = 0; q < 8; q++) {
        uint32_t v = colrun[q];
        v = max(v, __shfl_xor_sync(0xffffffffu, v, 4));
        v = max(v, __shfl_xor_sync(0xffffffffu, v, 8));
        v = max(v, __shfl_xor_sync(0xffffffffu, v, 16));
        colrun[q] = v;
    }
    if ((lane >> 2) == 0) {
#pragma unroll
        for (int nf = 0; nf < 4; nf++)
#pragma unroll
            for (int eb = 0; eb < 2; eb++) {
                int col = jt * 128 + wj * 32 + nf * 8 + 2 * lane + eb;
                atomicMax(&g_packed[col], colrun[nf * 2 + eb]);
            }
    }
}

__device__ __forceinline__ void flush_rows(uint32_t run[8], int it, int wi, int lane) {
#pragma unroll
    for (int q = 0; q < 8; q++) {
        uint32_t v = run[q];
        v = max(v, __shfl_xor_sync(0xffffffffu, v, 1));
        v = max(v, __shfl_xor_sync(0xffffffffu, v, 2));
        run[q] = v;
    }
    if ((lane & 3) == 0) {
#pragma unroll
        for (int mf = 0; mf < 4; mf++)
#pragma unroll
            for (int h = 0; h < 2; h++) {
                int row = it * 128 + wi * 64 + mf * 16 + (lane >> 2) + 8 * h;
                atomicMax(&g_packed[row], run[mf * 2 + h]);
            }
    }
}

__global__ __launch_bounds__(256, 2)
void mine_kernel() {
    extern __shared__ __half smh[];
    __half* sA = smh;
    __half* sB[2] = { smh + TILEH, smh + 2 * TILEH };

    const int tid = threadIdx.x, lane = tid & 31, wid = tid >> 5;
    const int wi = wid & 1, wj = wid >> 1;
    const int k = blockIdx.x;
    // spread the 8 heavy (8-tile) CTAs across distinct SMs: heavy iff k%37==0
    const int start = 7 * k + (k + 36) / 37;     // 7k + #heavies before k
    const int cnt = 7 + ((k % 37) == 0 ? 1 : 0);

    const int g8 = lane >> 3, l7 = lane & 7;
    const uint32_t sA_u = smem_u32(sA);
    const uint32_t sB_u[2] = { smem_u32(sB[0]), smem_u32(sB[1]) };
    uint32_t aOff[4], bOff[2];
#pragma unroll
    for (int mf = 0; mf < 4; mf++)
        aOff[mf] = (uint32_t)(((wi * 64 + mf * 16 + (g8 & 1) * 8 + l7) * LDH
                               + (g8 >> 1) * 8) * 2);
#pragma unroll
    for (int p = 0; p < 2; p++)
        bOff[p] = (uint32_t)(((wj * 32 + p * 16 + (g8 >> 1) * 8 + l7) * LDH
                               + (g8 & 1) * 8) * 2);

    auto loadA = [&](int it) {
#pragma unroll
        for (int i = 0; i < 8; i++) {
            int idx = tid + i * 256, r = idx >> 4, c = idx & 15;
            cp16(&sA[r * LDH + c * 8], g_embh + (size_t)(it * 128 + r) * DIM + c * 8);
        }
    };
    auto loadB = [&](__half* dst, int jt) {
#pragma unroll
        for (int i = 0; i < 8; i++) {
            int idx = tid + i * 256, r = idx >> 4, c = idx & 15;
            cp16(&dst[r * LDH + c * 8], g_embh + (size_t)(jt * 128 + r) * DIM + c * 8);
        }
    };

    int it0, jt0;
    dec_tile(start, it0, jt0);
    loadA(it0); loadB(sB[0], jt0);
    cpcommit();
    if (cnt > 1) { int i1, j1; dec_tile(start + 1, i1, j1); loadB(sB[1], j1); }
    cpcommit();

    int cur_it = it0;
    uint32_t run[8];
#pragma unroll
    for (int q = 0; q < 8; q++) run[q] = 0u;

    for (int s = 0; s < cnt; s++) {
        int it, jt;
        dec_tile(start + s, it, jt);
        if (it != cur_it) {
            flush_rows(run, cur_it, wi, lane);
#pragma unroll
            for (int q = 0; q < 8; q++) run[q] = 0u;
            cpwait<0>(); __syncthreads();
            loadA(it); cpcommit();
            cpwait<0>(); __syncthreads();
            cur_it = it;
        } else {
            cpwait<1>(); __syncthreads();
        }
        const uint32_t bBu = sB_u[s & 1];

        float acc[4][4][4];
#pragma unroll
        for (int mf = 0; mf < 4; mf++)
#pragma unroll
            for (int nf = 0; nf < 4; nf++)
#pragma unroll
                for (int e = 0; e < 4; e++) acc[mf][nf][e] = 2.0f;  // bias folded in

#pragma unroll
        for (int ks = 0; ks < 8; ks++) {
            const uint32_t koff = (uint32_t)(ks * 16 * 2);
            uint32_t a[4][4], b[4][2];
#pragma unroll
            for (int mf = 0; mf < 4; mf++)
                ldsm4(a[mf], sA_u + aOff[mf] + koff);
#pragma unroll
            for (int p = 0; p < 2; p++) {
                uint32_t t4[4];
                ldsm4(t4, bBu + bOff[p] + koff);
                b[p * 2][0] = t4[0]; b[p * 2][1] = t4[1];
                b[p * 2 + 1][0] = t4[2]; b[p * 2 + 1][1] = t4[3];
            }
#pragma unroll
            for (int mf = 0; mf < 4; mf++)
#pragma unroll
                for (int nf = 0; nf < 4; nf++)
                    mma16(acc[mf][nf], a[mf], b[nf]);
        }
        __syncthreads();

        if (s + 2 < cnt) {
            int i2, j2;
            dec_tile(start + s + 2, i2, j2);
            loadB(sB[s & 1], j2);
            cpcommit();
        }

        uint32_t jc[8];
#pragma unroll
        for (int nf = 0; nf < 4; nf++)
#pragma unroll
            for (int eb = 0; eb < 2; eb++)
                jc[nf * 2 + eb] =
                    (uint32_t)(8191 - (jt * 128 + wj * 32 + nf * 8 + 2 * (lane & 3) + eb));

        if (it == jt) {
            mine_rows<true>(acc, jc, run, wi, wj, lane);
        } else {
            mine_rows<false>(acc, jc, run, wi, wj, lane);
            mine_cols(acc, it, jt, wi, wj, lane);
        }
    }
    flush_rows(run, cur_it, wi, lane);
}

// ---------------------------------------------------------------------------
__global__ void flag_kernel(const int* __restrict__ labels) {
    int row = blockIdx.x * 256 + threadIdx.x;
    uint32_t pk = g_packed[row];
    int ni = 8191 - (int)(pk & 0x1FFFu);
    if (labels[ni] == labels[row]) {
        int s = atomicAdd(&g_nflag, 1);
        if (s < MAXFLAG) {
            g_flagrows[s] = row;
            g_ni[row] = -1;
            g_patch[row] = 0xFFFFFFFFu;
        } else {
            g_ni[row] = ni;   // overflow fallback (never expected)
        }
    } else {
        g_ni[row] = ni;
    }
}

// ---------------------------------------------------------------------------
// parallel exact rescan, coalesced: grid (MAXFLAG, 32)
// ---------------------------------------------------------------------------
__global__ void patch_kernel(const float* __restrict__ emb, const int* __restrict__ labels) {
    int f = blockIdx.x;
    if (f >= g_nflag) return;
    int row = g_flagrows[f];
    int li = labels[row];
    int tid = threadIdx.x, lane = tid & 31, w = tid >> 5;
    float4 av = *reinterpret_cast<const float4*>(emb + (size_t)row * DIM + lane * 4);
    float sqr = g_sq[row];
    uint32_t best = 0xFFFFFFFFu;
    int jbase = blockIdx.y * 256 + w * 32;
#pragma unroll 4
    for (int kk = 0; kk < 32; kk++) {
        int j = jbase + kk;
        float4 bv = *reinterpret_cast<const float4*>(emb + (size_t)j * DIM + lane * 4);
        float d = av.x * bv.x + av.y * bv.y + av.z * bv.z + av.w * bv.w;
#pragma unroll
        for (int o = 16; o; o >>= 1) d += __shfl_xor_sync(0xffffffffu, d, o);
        if (labels[j] != li) {
            float d2 = fmaxf(sqr + g_sq[j] - 2.f * d, 0.f);
            uint32_t pk = (__float_as_uint(d2) & 0xFFFFE000u) | (uint32_t)j;
            best = min(best, pk);
        }
    }
    if (lane == 0) atomicMin(&g_patch[row], best);
}

// ---------------------------------------------------------------------------
// finalize + fused final reduction (last block reduces all partials)
// ---------------------------------------------------------------------------
__global__ void finalize_kernel(const float* __restrict__ emb, float* __restrict__ out) {
    __shared__ float s_tri[8];
    __shared__ int   s_cnt[8];
    __shared__ int   s_last;
    int wid = threadIdx.x >> 5, lane = threadIdx.x & 31;
    int row = blockIdx.x * 8 + wid;
    int pi = g_pi[row];
    int ni = g_ni[row];
    if (ni < 0) ni = (int)(g_patch[row] & 0x1FFFu);
    bool valid = (pi >= 0);
    float per = 0.f;
    if (valid) {
        const float eps = 1e-6f;
        float4 a = *reinterpret_cast<const float4*>(emb + (size_t)row * DIM + lane * 4);
        float4 p = *reinterpret_cast<const float4*>(emb + (size_t)pi * DIM + lane * 4);
        float4 n = *reinterpret_cast<const float4*>(emb + (size_t)ni * DIM + lane * 4);
        float dx = a.x - p.x + eps, dy = a.y - p.y + eps, dz = a.z - p.z + eps, dw = a.w - p.w + eps;
        float sp = dx * dx + dy * dy + dz * dz + dw * dw;
        dx = a.x - n.x + eps; dy = a.y - n.y + eps; dz = a.z - n.z + eps; dw = a.w - n.w + eps;
        float sn = dx * dx + dy * dy + dz * dz + dw * dw;
#pragma unroll
        for (int off = 16; off; off >>= 1) {
            sp += __shfl_xor_sync(0xffffffffu, sp, off);
            sn += __shfl_xor_sync(0xffffffffu, sn, off);
        }
        per = fmaxf(sqrtf(sp) - sqrtf(sn) + 0.5f, 0.f);
    }
    if (lane == 0) { s_tri[wid] = valid ? per : 0.f; s_cnt[wid] = valid ? 1 : 0; }
    __syncthreads();
    if (threadIdx.x == 0) {
        float b = 0.f; int c = 0;
#pragma unroll
        for (int w = 0; w < 8; w++) { b += s_tri[w]; c += s_cnt[w]; }
        g_tri_part[blockIdx.x] = b;
        g_cnt_part[blockIdx.x] = c;
        __threadfence();
        s_last = (atomicAdd(&g_done, 1) == (int)gridDim.x - 1);
    }
    __syncthreads();
    if (s_last) {
        __shared__ float sce[8], str[8]; __shared__ int scn[8];
        int t = threadIdx.x;
        float ce = 0.f, tri = 0.f; int c = 0;
#pragma unroll
        for (int i = 0; i < 4; i++) {
            int idx = t + i * 256;
            ce  += g_ce_part[idx];
            tri += g_tri_part[idx];
            c   += g_cnt_part[idx];
        }
#pragma unroll
        for (int o = 16; o; o >>= 1) {
            ce  += __shfl_xor_sync(0xffffffffu, ce, o);
            tri += __shfl_xor_sync(0xffffffffu, tri, o);
            c   += __shfl_xor_sync(0xffffffffu, c, o);
        }
        if (lane == 0) { sce[wid] = ce; str[wid] = tri; scn[wid] = c; }
        __syncthreads();
        if (t == 0) {
            float tc = 0.f, tt = 0.f; int tn = 0;
#pragma unroll
            for (int i = 0; i < 8; i++) { tc += sce[i]; tt += str[i]; tn += scn[i]; }
            out[0] = tc * (1.0f / (float)BATCH) + (tn > 0 ? tt / (float)tn : 0.f);
        }
    }
}

// ---------------------------------------------------------------------------
extern "C" void kernel_launch(void* const* d_in, const int* in_sizes, int n_in,
                              void* d_out, int out_size) {
    const float* logits = (const float*)d_in[0];
    const float* emb    = (const float*)d_in[1];
    const int*   labels = (const int*)d_in[2];
    float* out = (float*)d_out;

    // Handles created exactly ONCE (first/correctness call), reused on the
    // capture call so no resources are created after the pre-capture baseline.
    static cudaStream_t s1 = nullptr, s2 = nullptr;
    static cudaEvent_t e0 = nullptr, e_prep = nullptr, e_pos = nullptr, e_ce = nullptr;
    if (s1 == nullptr) {
        cudaStreamCreateWithFlags(&s1, cudaStreamNonBlocking);
        cudaStreamCreateWithFlags(&s2, cudaStreamNonBlocking);
        cudaEventCreateWithFlags(&e0,     cudaEventDisableTiming);
        cudaEventCreateWithFlags(&e_prep, cudaEventDisableTiming);
        cudaEventCreateWithFlags(&e_pos,  cudaEventDisableTiming);
        cudaEventCreateWithFlags(&e_ce,   cudaEventDisableTiming);
        cudaFuncSetAttribute(mine_kernel, cudaFuncAttributeMaxDynamicSharedMemorySize, SMEM_BYTES);
    }

    cudaEventRecord(e0, 0);
    cudaStreamWaitEvent(s1, e0, 0);
    cudaStreamWaitEvent(s2, e0, 0);

    // main chain
    prep_kernel<<<BATCH / 8, 256>>>(emb);
    cudaEventRecord(e_prep, 0);
    mine_kernel<<<NCTA, 256, SMEM_BYTES>>>();
    flag_kernel<<<32, 256>>>(labels);
    {
        dim3 pg(MAXFLAG, 32);
        patch_kernel<<<pg, 256>>>(emb, labels);
    }

    // side chain 1: cross entropy
    ce_kernel<<<BATCH / 8, 256, 0, s1>>>(logits, labels);
    cudaEventRecord(e_ce, s1);

    // side chain 2: class grouping + hardest positive
    class_kernel<<<1, 1024, 0, s2>>>(labels);
    cudaStreamWaitEvent(s2, e_prep, 0);
    pos_kernel<<<BATCH / 8, 256, 0, s2>>>(emb, labels);
    cudaEventRecord(e_pos, s2);

    // join (finalize's last block also does the final reduction incl. ce)
    cudaStreamWaitEvent(0, e_pos, 0);
    cudaStreamWaitEvent(0, e_ce, 0);
    finalize_kernel<<<BATCH / 8, 256>>>(emb, out);
}